// round 6
// baseline (speedup 1.0000x reference)
#include <cuda_runtime.h>

// Device-global for the 4x4 doubly-stochastic matrix H.
__device__ float g_H[16];

// ---------------------------------------------------------------------------
// Kernel 1: warp-parallel Sinkhorn (~2us). Lane l<16 owns element
// (i=l/4, j=l%4). Row sums via shfl_xor width-4; col sums via shfl_xor
// {4,8} width-16. PDL trigger after fenced g_H writes.
// ---------------------------------------------------------------------------
__global__ void sinkhorn_kernel(const float* __restrict__ H_raw) {
    const int l = threadIdx.x;
    const int e = l & 15;
    float a = fabsf(H_raw[e]) + 1e-8f;

    #pragma unroll 1
    for (int it = 0; it < 20; it++) {
        float s = a;
        s += __shfl_xor_sync(0xFFFFFFFFu, s, 1, 4);
        s += __shfl_xor_sync(0xFFFFFFFFu, s, 2, 4);
        a *= __frcp_rn(s);
        float c = a;
        c += __shfl_xor_sync(0xFFFFFFFFu, c, 4, 16);
        c += __shfl_xor_sync(0xFFFFFFFFu, c, 8, 16);
        a *= __frcp_rn(c);
    }

    if (l < 16) g_H[l] = a;
    __threadfence();
    cudaTriggerProgrammaticLaunchCompletion();
}

// ---------------------------------------------------------------------------
// Kernel 2: streaming mix, 4 bt rows per block (grid 4096), 16 front-batched
// float4 loads per thread (MLP=16). out[bt,n,d] = sum_m H[n,m]*x[bt,m,d].
// Loads are H-independent and issued before cudaGridDependencySynchronize().
// ---------------------------------------------------------------------------
__global__ __launch_bounds__(256) void mix_kernel(const float4* __restrict__ x,
                                                  float4* __restrict__ out) {
    const int q = threadIdx.x;
    const size_t base = (size_t)blockIdx.x * 4096;  // 4 bt rows * 1024 float4

    const float4* __restrict__ xb = x + base;
    float4* __restrict__ ob       = out + base;

    // Front-batch all 16 stream loads (4 rows x 4 streams), evict-first.
    float4 v[4][4];
    #pragma unroll
    for (int r = 0; r < 4; r++)
        #pragma unroll
        for (int m = 0; m < 4; m++)
            v[r][m] = __ldcs(xb + r * 1024 + m * 256 + q);

    // Wait for the sinkhorn kernel's trigger (overlapped with loads above).
    cudaGridDependencySynchronize();

    float h[16];
    #pragma unroll
    for (int i = 0; i < 16; i++) h[i] = __ldg(&g_H[i]);

    #pragma unroll
    for (int r = 0; r < 4; r++) {
        #pragma unroll
        for (int n = 0; n < 4; n++) {
            const float h0 = h[n * 4 + 0], h1 = h[n * 4 + 1];
            const float h2 = h[n * 4 + 2], h3 = h[n * 4 + 3];
            float4 o;
            o.x = h0 * v[r][0].x + h1 * v[r][1].x + h2 * v[r][2].x + h3 * v[r][3].x;
            o.y = h0 * v[r][0].y + h1 * v[r][1].y + h2 * v[r][2].y + h3 * v[r][3].y;
            o.z = h0 * v[r][0].z + h1 * v[r][1].z + h2 * v[r][2].z + h3 * v[r][3].z;
            o.w = h0 * v[r][0].w + h1 * v[r][1].w + h2 * v[r][2].w + h3 * v[r][3].w;
            __stcs(ob + r * 1024 + n * 256 + q, o);
        }
    }
}

extern "C" void kernel_launch(void* const* d_in, const int* in_sizes, int n_in,
                              void* d_out, int out_size) {
    const float* x     = (const float*)d_in[0];  // [4, 4096, 4, 1024] fp32
    const float* H_raw = (const float*)d_in[1];  // [4, 4]
    float* out         = (float*)d_out;          // same shape as x

    sinkhorn_kernel<<<1, 32>>>(H_raw);

    const int BT = 4 * 4096;  // 16384 (b,t) pairs, 4 per block

    cudaLaunchConfig_t cfg = {};
    cfg.gridDim  = dim3(BT / 4, 1, 1);
    cfg.blockDim = dim3(256, 1, 1);
    cfg.dynamicSmemBytes = 0;
    cfg.stream = 0;
    cudaLaunchAttribute attr[1];
    attr[0].id = cudaLaunchAttributeProgrammaticStreamSerialization;
    attr[0].val.programmaticStreamSerializationAllowed = 1;
    cfg.attrs = attr;
    cfg.numAttrs = 1;

    cudaLaunchKernelEx(&cfg, mix_kernel, (const float4*)x, (float4*)out);
    (void)in_sizes; (void)n_in; (void)out_size;
}

// round 7
// speedup vs baseline: 1.0546x; 1.0546x over previous
#include <cuda_runtime.h>

// Device-global for the 4x4 doubly-stochastic matrix H.
__device__ float g_H[16];

// ---------------------------------------------------------------------------
// Kernel 1: warp-parallel Sinkhorn (~2us). Lane l<16 owns element
// (i=l/4, j=l%4). Row sums via shfl_xor width-4; col sums via shfl_xor
// {4,8} width-16. PDL trigger after fenced g_H writes.
// ---------------------------------------------------------------------------
__global__ void sinkhorn_kernel(const float* __restrict__ H_raw) {
    const int l = threadIdx.x;
    const int e = l & 15;
    float a = fabsf(H_raw[e]) + 1e-8f;

    #pragma unroll 1
    for (int it = 0; it < 20; it++) {
        float s = a;
        s += __shfl_xor_sync(0xFFFFFFFFu, s, 1, 4);
        s += __shfl_xor_sync(0xFFFFFFFFu, s, 2, 4);
        a *= __frcp_rn(s);
        float c = a;
        c += __shfl_xor_sync(0xFFFFFFFFu, c, 4, 16);
        c += __shfl_xor_sync(0xFFFFFFFFu, c, 8, 16);
        a *= __frcp_rn(c);
    }

    if (l < 16) g_H[l] = a;
    __threadfence();
    cudaTriggerProgrammaticLaunchCompletion();
}

// ---------------------------------------------------------------------------
// Kernel 2: streaming mix. Proven per-thread profile (8 front-batched float4
// loads, MLP=8), but 128-thread blocks covering ONE bt row each (grid 16384)
// -> ~2x resident blocks/SM vs the 256-thread version at the same MLP.
//   out[bt, n, d] = sum_m H[n,m] * x[bt, m, d]
//   Row layout: 4 streams x 256 float4. Thread q handles float4 lanes q and
//   q+128 of each stream.
// ---------------------------------------------------------------------------
__global__ __launch_bounds__(128) void mix_kernel(const float4* __restrict__ x,
                                                  float4* __restrict__ out) {
    const int q = threadIdx.x;                       // 0..127
    const size_t base = (size_t)blockIdx.x * 1024;   // one bt row

    const float4* __restrict__ xb = x + base;
    float4* __restrict__ ob       = out + base;

    // Front-batch 8 stream loads (4 streams x 2 chunks), evict-first.
    float4 v[4][2];
    #pragma unroll
    for (int m = 0; m < 4; m++) {
        v[m][0] = __ldcs(xb + m * 256 + q);
        v[m][1] = __ldcs(xb + m * 256 + 128 + q);
    }

    // Wait for the sinkhorn kernel's trigger (overlapped with loads above).
    cudaGridDependencySynchronize();

    float h[16];
    #pragma unroll
    for (int i = 0; i < 16; i++) h[i] = __ldg(&g_H[i]);

    #pragma unroll
    for (int n = 0; n < 4; n++) {
        const float h0 = h[n * 4 + 0], h1 = h[n * 4 + 1];
        const float h2 = h[n * 4 + 2], h3 = h[n * 4 + 3];
        #pragma unroll
        for (int k = 0; k < 2; k++) {
            float4 o;
            o.x = h0 * v[0][k].x + h1 * v[1][k].x + h2 * v[2][k].x + h3 * v[3][k].x;
            o.y = h0 * v[0][k].y + h1 * v[1][k].y + h2 * v[2][k].y + h3 * v[3][k].y;
            o.z = h0 * v[0][k].z + h1 * v[1][k].z + h2 * v[2][k].z + h3 * v[3][k].z;
            o.w = h0 * v[0][k].w + h1 * v[1][k].w + h2 * v[2][k].w + h3 * v[3][k].w;
            __stcs(ob + n * 256 + k * 128 + q, o);
        }
    }
}

extern "C" void kernel_launch(void* const* d_in, const int* in_sizes, int n_in,
                              void* d_out, int out_size) {
    const float* x     = (const float*)d_in[0];  // [4, 4096, 4, 1024] fp32
    const float* H_raw = (const float*)d_in[1];  // [4, 4]
    float* out         = (float*)d_out;          // same shape as x

    sinkhorn_kernel<<<1, 32>>>(H_raw);

    const int BT = 4 * 4096;  // 16384 bt rows, one per block

    cudaLaunchConfig_t cfg = {};
    cfg.gridDim  = dim3(BT, 1, 1);
    cfg.blockDim = dim3(128, 1, 1);
    cfg.dynamicSmemBytes = 0;
    cfg.stream = 0;
    cudaLaunchAttribute attr[1];
    attr[0].id = cudaLaunchAttributeProgrammaticStreamSerialization;
    attr[0].val.programmaticStreamSerializationAllowed = 1;
    cfg.attrs = attr;
    cfg.numAttrs = 1;

    cudaLaunchKernelEx(&cfg, mix_kernel, (const float4*)x, (float4*)out);
    (void)in_sizes; (void)n_in; (void)out_size;
}

// round 8
// speedup vs baseline: 1.0589x; 1.0041x over previous
#include <cuda_runtime.h>

// Device-global for the 4x4 doubly-stochastic matrix H.
__device__ float g_H[16];

__device__ __forceinline__ float rcp_approx(float x) {
    float r;
    asm("rcp.approx.f32 %0, %1;" : "=f"(r) : "f"(x));
    return r;
}

// ---------------------------------------------------------------------------
// Kernel 1: single-thread Sinkhorn with row/col ILP and rcp.approx.
// Chain ~56 cyc/iter x 20 iters ~= 1120 cyc ~= 0.6us (vs ~2us for the
// shuffle version: 80 lat-26 SHFLs + correctly-rounded rcp sequences).
// PDL trigger after fenced g_H writes.
// ---------------------------------------------------------------------------
__global__ void sinkhorn_kernel(const float* __restrict__ H_raw) {
    if (threadIdx.x == 0) {
        float A[16];
        #pragma unroll
        for (int i = 0; i < 16; i++) A[i] = fabsf(__ldg(&H_raw[i])) + 1e-8f;

        #pragma unroll 1
        for (int it = 0; it < 20; it++) {
            // Row normalize: 4 independent rows (ILP), tree sums.
            #pragma unroll
            for (int i = 0; i < 4; i++) {
                float s = (A[4*i+0] + A[4*i+1]) + (A[4*i+2] + A[4*i+3]);
                float inv = rcp_approx(s);
                #pragma unroll
                for (int j = 0; j < 4; j++) A[4*i+j] *= inv;
            }
            // Col normalize: 4 independent cols (ILP), tree sums.
            #pragma unroll
            for (int j = 0; j < 4; j++) {
                float s = (A[0+j] + A[4+j]) + (A[8+j] + A[12+j]);
                float inv = rcp_approx(s);
                #pragma unroll
                for (int i = 0; i < 4; i++) A[4*i+j] *= inv;
            }
        }
        #pragma unroll
        for (int i = 0; i < 16; i++) g_H[i] = A[i];
        __threadfence();
    }
    cudaTriggerProgrammaticLaunchCompletion();
}

// ---------------------------------------------------------------------------
// Kernel 2: the proven optimum streaming mix (256 thr, 2 bt rows per block,
// 8 front-batched float4 loads = MLP=8, evict-first hints).
//   out[bt, n, d] = sum_m H[n,m] * x[bt, m, d]
// Loads are H-independent and issued before cudaGridDependencySynchronize().
// ---------------------------------------------------------------------------
__global__ __launch_bounds__(256) void mix_kernel(const float4* __restrict__ x,
                                                  float4* __restrict__ out) {
    const int bt0 = blockIdx.x * 2;
    const int q   = threadIdx.x;

    const float4* __restrict__ xa = x + (size_t)bt0 * 1024;
    const float4* __restrict__ xb = xa + 1024;
    float4* __restrict__ oa       = out + (size_t)bt0 * 1024;
    float4* __restrict__ ob       = oa + 1024;

    // Front-batch all 8 stream loads (MLP=8), evict-first.
    float4 a0 = __ldcs(xa + 0 * 256 + q);
    float4 a1 = __ldcs(xa + 1 * 256 + q);
    float4 a2 = __ldcs(xa + 2 * 256 + q);
    float4 a3 = __ldcs(xa + 3 * 256 + q);
    float4 b0 = __ldcs(xb + 0 * 256 + q);
    float4 b1 = __ldcs(xb + 1 * 256 + q);
    float4 b2 = __ldcs(xb + 2 * 256 + q);
    float4 b3 = __ldcs(xb + 3 * 256 + q);

    // Wait for the sinkhorn kernel's trigger (overlapped with loads above).
    cudaGridDependencySynchronize();

    float h[16];
    #pragma unroll
    for (int i = 0; i < 16; i++) h[i] = __ldg(&g_H[i]);

    #pragma unroll
    for (int n = 0; n < 4; n++) {
        const float h0 = h[n * 4 + 0], h1 = h[n * 4 + 1];
        const float h2 = h[n * 4 + 2], h3 = h[n * 4 + 3];
        float4 o;
        o.x = h0 * a0.x + h1 * a1.x + h2 * a2.x + h3 * a3.x;
        o.y = h0 * a0.y + h1 * a1.y + h2 * a2.y + h3 * a3.y;
        o.z = h0 * a0.z + h1 * a1.z + h2 * a2.z + h3 * a3.z;
        o.w = h0 * a0.w + h1 * a1.w + h2 * a2.w + h3 * a3.w;
        __stcs(oa + n * 256 + q, o);
    }
    #pragma unroll
    for (int n = 0; n < 4; n++) {
        const float h0 = h[n * 4 + 0], h1 = h[n * 4 + 1];
        const float h2 = h[n * 4 + 2], h3 = h[n * 4 + 3];
        float4 o;
        o.x = h0 * b0.x + h1 * b1.x + h2 * b2.x + h3 * b3.x;
        o.y = h0 * b0.y + h1 * b1.y + h2 * b2.y + h3 * b3.y;
        o.z = h0 * b0.z + h1 * b1.z + h2 * b2.z + h3 * b3.z;
        o.w = h0 * b0.w + h1 * b1.w + h2 * b2.w + h3 * b3.w;
        __stcs(ob + n * 256 + q, o);
    }
}

extern "C" void kernel_launch(void* const* d_in, const int* in_sizes, int n_in,
                              void* d_out, int out_size) {
    const float* x     = (const float*)d_in[0];  // [4, 4096, 4, 1024] fp32
    const float* H_raw = (const float*)d_in[1];  // [4, 4]
    float* out         = (float*)d_out;          // same shape as x

    sinkhorn_kernel<<<1, 32>>>(H_raw);

    const int BT = 4 * 4096;  // 16384 (b,t) pairs, 2 per block

    cudaLaunchConfig_t cfg = {};
    cfg.gridDim  = dim3(BT / 2, 1, 1);
    cfg.blockDim = dim3(256, 1, 1);
    cfg.dynamicSmemBytes = 0;
    cfg.stream = 0;
    cudaLaunchAttribute attr[1];
    attr[0].id = cudaLaunchAttributeProgrammaticStreamSerialization;
    attr[0].val.programmaticStreamSerializationAllowed = 1;
    cfg.attrs = attr;
    cfg.numAttrs = 1;

    cudaLaunchKernelEx(&cfg, mix_kernel, (const float4*)x, (float4*)out);
    (void)in_sizes; (void)n_in; (void)out_size;
}

// round 10
// speedup vs baseline: 1.0685x; 1.0090x over previous
#include <cuda_runtime.h>

// Device-global for the 4x4 doubly-stochastic matrix H.
__device__ float g_H[16];

__device__ __forceinline__ float rcp_approx(float x) {
    float r;
    asm("rcp.approx.f32 %0, %1;" : "=f"(r) : "f"(x));
    return r;
}

// ---------------------------------------------------------------------------
// Kernel 1: single-thread Sinkhorn with row/col ILP and rcp.approx (~0.6us).
// PDL trigger after fenced g_H writes.
// ---------------------------------------------------------------------------
__global__ void sinkhorn_kernel(const float* __restrict__ H_raw) {
    if (threadIdx.x == 0) {
        float A[16];
        #pragma unroll
        for (int i = 0; i < 16; i++) A[i] = fabsf(__ldg(&H_raw[i])) + 1e-8f;

        #pragma unroll 1
        for (int it = 0; it < 20; it++) {
            #pragma unroll
            for (int i = 0; i < 4; i++) {
                float s = (A[4*i+0] + A[4*i+1]) + (A[4*i+2] + A[4*i+3]);
                float inv = rcp_approx(s);
                #pragma unroll
                for (int j = 0; j < 4; j++) A[4*i+j] *= inv;
            }
            #pragma unroll
            for (int j = 0; j < 4; j++) {
                float s = (A[0+j] + A[4+j]) + (A[8+j] + A[12+j]);
                float inv = rcp_approx(s);
                #pragma unroll
                for (int i = 0; i < 4; i++) A[4*i+j] *= inv;
            }
        }
        #pragma unroll
        for (int i = 0; i < 16; i++) g_H[i] = A[i];
        __threadfence();
    }
    cudaTriggerProgrammaticLaunchCompletion();
}

// ---------------------------------------------------------------------------
// Kernel 2: streaming mix. Per-thread profile identical to the proven
// optimum (8 front-batched float4 loads = MLP=8, evict-first), but 512-thread
// blocks covering 4 bt rows each (grid 4096): same 1024 threads/SM residency,
// half the CTA launch/drain events and wave transitions.
//   out[bt, n, d] = sum_m H[n,m] * x[bt, m, d]
//   Threads 0..255 handle rows bt0/bt0+1; threads 256..511 rows bt0+2/bt0+3.
// ---------------------------------------------------------------------------
__global__ __launch_bounds__(512) void mix_kernel(const float4* __restrict__ x,
                                                  float4* __restrict__ out) {
    const int q    = threadIdx.x & 255;          // float4 lane within a row
    const int half = threadIdx.x >> 8;           // 0 or 1: which row-pair
    const size_t bt0 = (size_t)blockIdx.x * 4 + half * 2;

    const float4* __restrict__ xa = x + bt0 * 1024;
    const float4* __restrict__ xb = xa + 1024;
    float4* __restrict__ oa       = out + bt0 * 1024;
    float4* __restrict__ ob       = oa + 1024;

    // Front-batch all 8 stream loads (MLP=8), evict-first.
    float4 a0 = __ldcs(xa + 0 * 256 + q);
    float4 a1 = __ldcs(xa + 1 * 256 + q);
    float4 a2 = __ldcs(xa + 2 * 256 + q);
    float4 a3 = __ldcs(xa + 3 * 256 + q);
    float4 b0 = __ldcs(xb + 0 * 256 + q);
    float4 b1 = __ldcs(xb + 1 * 256 + q);
    float4 b2 = __ldcs(xb + 2 * 256 + q);
    float4 b3 = __ldcs(xb + 3 * 256 + q);

    // Wait for the sinkhorn kernel's trigger (overlapped with loads above).
    cudaGridDependencySynchronize();

    float h[16];
    #pragma unroll
    for (int i = 0; i < 16; i++) h[i] = __ldg(&g_H[i]);

    #pragma unroll
    for (int n = 0; n < 4; n++) {
        const float h0 = h[n * 4 + 0], h1 = h[n * 4 + 1];
        const float h2 = h[n * 4 + 2], h3 = h[n * 4 + 3];
        float4 o;
        o.x = h0 * a0.x + h1 * a1.x + h2 * a2.x + h3 * a3.x;
        o.y = h0 * a0.y + h1 * a1.y + h2 * a2.y + h3 * a3.y;
        o.z = h0 * a0.z + h1 * a1.z + h2 * a2.z + h3 * a3.z;
        o.w = h0 * a0.w + h1 * a1.w + h2 * a2.w + h3 * a3.w;
        __stcs(oa + n * 256 + q, o);
    }
    #pragma unroll
    for (int n = 0; n < 4; n++) {
        const float h0 = h[n * 4 + 0], h1 = h[n * 4 + 1];
        const float h2 = h[n * 4 + 2], h3 = h[n * 4 + 3];
        float4 o;
        o.x = h0 * b0.x + h1 * b1.x + h2 * b2.x + h3 * b3.x;
        o.y = h0 * b0.y + h1 * b1.y + h2 * b2.y + h3 * b3.y;
        o.z = h0 * b0.z + h1 * b1.z + h2 * b2.z + h3 * b3.z;
        o.w = h0 * b0.w + h1 * b1.w + h2 * b2.w + h3 * b3.w;
        __stcs(ob + n * 256 + q, o);
    }
}

extern "C" void kernel_launch(void* const* d_in, const int* in_sizes, int n_in,
                              void* d_out, int out_size) {
    const float* x     = (const float*)d_in[0];  // [4, 4096, 4, 1024] fp32
    const float* H_raw = (const float*)d_in[1];  // [4, 4]
    float* out         = (float*)d_out;          // same shape as x

    sinkhorn_kernel<<<1, 32>>>(H_raw);

    const int BT = 4 * 4096;  // 16384 (b,t) pairs, 4 per block

    cudaLaunchConfig_t cfg = {};
    cfg.gridDim  = dim3(BT / 4, 1, 1);
    cfg.blockDim = dim3(512, 1, 1);
    cfg.dynamicSmemBytes = 0;
    cfg.stream = 0;
    cudaLaunchAttribute attr[1];
    attr[0].id = cudaLaunchAttributeProgrammaticStreamSerialization;
    attr[0].val.programmaticStreamSerializationAllowed = 1;
    cfg.attrs = attr;
    cfg.numAttrs = 1;

    cudaLaunchKernelEx(&cfg, mix_kernel, (const float4*)x, (float4*)out);
    (void)in_sizes; (void)n_in; (void)out_size;
}

// round 11
// speedup vs baseline: 1.0758x; 1.0068x over previous
#include <cuda_runtime.h>

// Device-global for the 4x4 doubly-stochastic matrix H (16B-aligned for LDG.128).
__device__ __align__(16) float g_H[16];

__device__ __forceinline__ float rcp_approx(float x) {
    float r;
    asm("rcp.approx.f32 %0, %1;" : "=f"(r) : "f"(x));
    return r;
}

// ---------------------------------------------------------------------------
// Kernel 1: single-thread Sinkhorn with row/col ILP and rcp.approx (~0.6us).
// PDL trigger after fenced g_H writes.
// ---------------------------------------------------------------------------
__global__ void sinkhorn_kernel(const float* __restrict__ H_raw) {
    if (threadIdx.x == 0) {
        float A[16];
        #pragma unroll
        for (int i = 0; i < 16; i++) A[i] = fabsf(__ldg(&H_raw[i])) + 1e-8f;

        #pragma unroll 1
        for (int it = 0; it < 20; it++) {
            #pragma unroll
            for (int i = 0; i < 4; i++) {
                float s = (A[4*i+0] + A[4*i+1]) + (A[4*i+2] + A[4*i+3]);
                float inv = rcp_approx(s);
                #pragma unroll
                for (int j = 0; j < 4; j++) A[4*i+j] *= inv;
            }
            #pragma unroll
            for (int j = 0; j < 4; j++) {
                float s = (A[0+j] + A[4+j]) + (A[8+j] + A[12+j]);
                float inv = rcp_approx(s);
                #pragma unroll
                for (int i = 0; i < 4; i++) A[4*i+j] *= inv;
            }
        }
        #pragma unroll
        for (int i = 0; i < 16; i++) g_H[i] = A[i];
        __threadfence();
    }
    cudaTriggerProgrammaticLaunchCompletion();
}

// ---------------------------------------------------------------------------
// Kernel 2: streaming mix — the proven optimum geometry (512 threads, 4 bt
// rows per block, grid 4096; per-thread: 8 front-batched float4 loads MLP=8,
// evict-first). One change vs R10: g_H read as 4x LDG.128 instead of 16
// scalar LDGs, shrinking the post-dependency-sync issue burst 4x.
//   out[bt, n, d] = sum_m H[n,m] * x[bt, m, d]
// ---------------------------------------------------------------------------
__global__ __launch_bounds__(512) void mix_kernel(const float4* __restrict__ x,
                                                  float4* __restrict__ out) {
    const int q    = threadIdx.x & 255;          // float4 lane within a row
    const int half = threadIdx.x >> 8;           // 0 or 1: which row-pair
    const size_t bt0 = (size_t)blockIdx.x * 4 + half * 2;

    const float4* __restrict__ xa = x + bt0 * 1024;
    const float4* __restrict__ xb = xa + 1024;
    float4* __restrict__ oa       = out + bt0 * 1024;
    float4* __restrict__ ob       = oa + 1024;

    // Front-batch all 8 stream loads (MLP=8), evict-first.
    float4 a0 = __ldcs(xa + 0 * 256 + q);
    float4 a1 = __ldcs(xa + 1 * 256 + q);
    float4 a2 = __ldcs(xa + 2 * 256 + q);
    float4 a3 = __ldcs(xa + 3 * 256 + q);
    float4 b0 = __ldcs(xb + 0 * 256 + q);
    float4 b1 = __ldcs(xb + 1 * 256 + q);
    float4 b2 = __ldcs(xb + 2 * 256 + q);
    float4 b3 = __ldcs(xb + 3 * 256 + q);

    // Wait for the sinkhorn kernel's trigger (overlapped with loads above).
    cudaGridDependencySynchronize();

    // H as 4 vectorized broadcast loads (rows of H).
    const float4* __restrict__ Hv = (const float4*)g_H;
    float4 hr[4];
    #pragma unroll
    for (int n = 0; n < 4; n++) hr[n] = __ldg(&Hv[n]);

    #pragma unroll
    for (int n = 0; n < 4; n++) {
        const float h0 = hr[n].x, h1 = hr[n].y, h2 = hr[n].z, h3 = hr[n].w;
        float4 o;
        o.x = h0 * a0.x + h1 * a1.x + h2 * a2.x + h3 * a3.x;
        o.y = h0 * a0.y + h1 * a1.y + h2 * a2.y + h3 * a3.y;
        o.z = h0 * a0.z + h1 * a1.z + h2 * a2.z + h3 * a3.z;
        o.w = h0 * a0.w + h1 * a1.w + h2 * a2.w + h3 * a3.w;
        __stcs(oa + n * 256 + q, o);
    }
    #pragma unroll
    for (int n = 0; n < 4; n++) {
        const float h0 = hr[n].x, h1 = hr[n].y, h2 = hr[n].z, h3 = hr[n].w;
        float4 o;
        o.x = h0 * b0.x + h1 * b1.x + h2 * b2.x + h3 * b3.x;
        o.y = h0 * b0.y + h1 * b1.y + h2 * b2.y + h3 * b3.y;
        o.z = h0 * b0.z + h1 * b1.z + h2 * b2.z + h3 * b3.z;
        o.w = h0 * b0.w + h1 * b1.w + h2 * b2.w + h3 * b3.w;
        __stcs(ob + n * 256 + q, o);
    }
}

extern "C" void kernel_launch(void* const* d_in, const int* in_sizes, int n_in,
                              void* d_out, int out_size) {
    const float* x     = (const float*)d_in[0];  // [4, 4096, 4, 1024] fp32
    const float* H_raw = (const float*)d_in[1];  // [4, 4]
    float* out         = (float*)d_out;          // same shape as x

    sinkhorn_kernel<<<1, 32>>>(H_raw);

    const int BT = 4 * 4096;  // 16384 (b,t) pairs, 4 per block

    cudaLaunchConfig_t cfg = {};
    cfg.gridDim  = dim3(BT / 4, 1, 1);
    cfg.blockDim = dim3(512, 1, 1);
    cfg.dynamicSmemBytes = 0;
    cfg.stream = 0;
    cudaLaunchAttribute attr[1];
    attr[0].id = cudaLaunchAttributeProgrammaticStreamSerialization;
    attr[0].val.programmaticStreamSerializationAllowed = 1;
    cfg.attrs = attr;
    cfg.numAttrs = 1;

    cudaLaunchKernelEx(&cfg, mix_kernel, (const float4*)x, (float4*)out);
    (void)in_sizes; (void)n_in; (void)out_size;
}